// round 16
// baseline (speedup 1.0000x reference)
#include <cuda_runtime.h>
#include <cuda_bf16.h>
#include <cuda_fp16.h>
#include <cstdint>

#define NMAX 50048
#define EMAX 800000
#define HD   128
#define GG   16

// Scratch (no cudaMalloc allowed)
__device__ __align__(16) float g_A[NMAX * HD];                 // fp32 h2 (pool input)
__device__ __align__(256) __half g_Hh[NMAX * HD];              // fp16 gather features
__device__ __align__(16) __nv_bfloat16 g_Zh[NMAX * HD];
__device__ __align__(16) __nv_bfloat16 g_Zl[NMAX * HD];
__device__ float g_sums[GG * HD];
__device__ float g_cnt[GG];
__device__ __align__(16) int g_rowptr[NMAX + 8];
__device__ __align__(16) int g_cursor[NMAX];
__device__ __align__(16) int g_rank[EMAX];
__device__ __align__(16) int g_csr[EMAX];
__device__ int   g_bflag[64];
__device__ int   g_bagg[64];
__device__ int   g_bincl[64];
__device__ __align__(16) __nv_bfloat16 g_Wbh[4 * 16384];
__device__ __align__(16) __nv_bfloat16 g_Wbl[4 * 16384];

// ================================================================ prep (+ h->fp16)
__global__ void prep_kernel(const float* __restrict__ h,
                            const float* __restrict__ W1a, const float* __restrict__ W2a,
                            const float* __restrict__ W1b, const float* __restrict__ W2b,
                            int n, int n4) {
    int idx = blockIdx.x * 256 + threadIdx.x;
    if (idx < n4) {
        float4 v = ((const float4*)h)[idx];
        __half2 a = __floats2half2_rn(v.x, v.y);
        __half2 b = __floats2half2_rn(v.z, v.w);
        uint2 p;
        p.x = *(uint32_t*)&a;
        p.y = *(uint32_t*)&b;
        ((uint2*)g_Hh)[idx] = p;
    }
    if (idx < n)  g_cursor[idx] = 0;
    if (idx < 64) g_bflag[idx] = 0;
    if (idx < GG * HD) g_sums[idx] = 0.f;
    if (idx < GG) g_cnt[idx] = 0.f;
    if (idx < 65536) {
        int w = idx >> 14, rem = idx & 16383;
        int nn = rem >> 7, k = rem & 127;
        const float* Wp = (w == 0) ? W1a : (w == 1) ? W2a : (w == 2) ? W1b : W2b;
        float v = Wp[k * 128 + nn];
        __nv_bfloat16 hi = __float2bfloat16(v);
        __nv_bfloat16 lo = __float2bfloat16(v - __bfloat162float(hi));
        g_Wbh[idx] = hi;
        g_Wbl[idx] = lo;
    }
}

// hist + rank, 8 edges/thread
__global__ void hist_kernel(const int* __restrict__ dst, int nE) {
    int base = (blockIdx.x * blockDim.x + threadIdx.x) * 8;
    if (base + 7 < nE) {
        int4 d0 = *(const int4*)(dst + base);
        int4 d1 = *(const int4*)(dst + base + 4);
        int r0 = atomicAdd(&g_cursor[d0.x], 1);
        int r1 = atomicAdd(&g_cursor[d0.y], 1);
        int r2 = atomicAdd(&g_cursor[d0.z], 1);
        int r3 = atomicAdd(&g_cursor[d0.w], 1);
        int r4 = atomicAdd(&g_cursor[d1.x], 1);
        int r5 = atomicAdd(&g_cursor[d1.y], 1);
        int r6 = atomicAdd(&g_cursor[d1.z], 1);
        int r7 = atomicAdd(&g_cursor[d1.w], 1);
        *(int4*)(g_rank + base)     = make_int4(r0, r1, r2, r3);
        *(int4*)(g_rank + base + 4) = make_int4(r4, r5, r6, r7);
    } else {
        for (int e = base; e < nE; e++) g_rank[e] = atomicAdd(&g_cursor[dst[e]], 1);
    }
}

// ---------------- decoupled-lookback scan, 8 counts/thread
__global__ void __launch_bounds__(1024) scan_fused_kernel(int n) {
    __shared__ int warpsums[32];
    __shared__ int s_off;
    int tid = threadIdx.x, lane = tid & 31, w = tid >> 5;
    int bid = blockIdx.x;
    int i8 = (bid * 1024 + tid) * 8;

    int v[8];
    if (i8 + 7 < n) {
        int4 a = *(const int4*)(g_cursor + i8);
        int4 b = *(const int4*)(g_cursor + i8 + 4);
        v[0] = a.x; v[1] = a.y; v[2] = a.z; v[3] = a.w;
        v[4] = b.x; v[5] = b.y; v[6] = b.z; v[7] = b.w;
    } else {
        #pragma unroll
        for (int j = 0; j < 8; j++) v[j] = (i8 + j < n) ? g_cursor[i8 + j] : 0;
    }
    int tsum = 0;
    #pragma unroll
    for (int j = 0; j < 8; j++) tsum += v[j];

    int x = tsum;
    #pragma unroll
    for (int o = 1; o < 32; o <<= 1) {
        int y = __shfl_up_sync(0xFFFFFFFFu, x, o);
        if (lane >= o) x += y;
    }
    if (lane == 31) warpsums[w] = x;
    __syncthreads();
    if (w == 0) {
        int y = warpsums[lane];
        #pragma unroll
        for (int o = 1; o < 32; o <<= 1) {
            int z = __shfl_up_sync(0xFFFFFFFFu, y, o);
            if (lane >= o) y += z;
        }
        warpsums[lane] = y;
    }
    __syncthreads();
    int incl = x + (w > 0 ? warpsums[w - 1] : 0);
    int total = warpsums[31];

    if (tid == 0) {
        if (bid == 0) {
            g_bincl[0] = total;
            __threadfence();
            atomicExch(&g_bflag[0], 2);
            s_off = 0;
        } else {
            g_bagg[bid] = total;
            __threadfence();
            atomicExch(&g_bflag[bid], 1);
            int run = 0, p = bid - 1;
            while (true) {
                int f;
                do { f = atomicAdd(&g_bflag[p], 0); } while (f == 0);
                if (f == 2) { run += atomicAdd(&g_bincl[p], 0); break; }
                run += atomicAdd(&g_bagg[p], 0);
                p--;
            }
            g_bincl[bid] = run + total;
            __threadfence();
            atomicExch(&g_bflag[bid], 2);
            s_off = run;
        }
    }
    __syncthreads();
    int run = s_off + incl - tsum;
    #pragma unroll
    for (int j = 0; j < 8; j++) {
        run += v[j];
        if (i8 + j < n) g_rowptr[i8 + j + 1] = run;
    }
    if (i8 == 0) g_rowptr[0] = 0;
}

// atomic-free fill, 8 edges/thread
__global__ void fill_kernel(const int* __restrict__ src, const int* __restrict__ dst, int nE) {
    int base = (blockIdx.x * blockDim.x + threadIdx.x) * 8;
    if (base + 7 < nE) {
        int4 d0 = *(const int4*)(dst + base);
        int4 d1 = *(const int4*)(dst + base + 4);
        int4 s0 = *(const int4*)(src + base);
        int4 s1 = *(const int4*)(src + base + 4);
        int4 r0 = *(const int4*)(g_rank + base);
        int4 r1 = *(const int4*)(g_rank + base + 4);
        g_csr[g_rowptr[d0.x] + r0.x] = s0.x;
        g_csr[g_rowptr[d0.y] + r0.y] = s0.y;
        g_csr[g_rowptr[d0.z] + r0.z] = s0.z;
        g_csr[g_rowptr[d0.w] + r0.w] = s0.w;
        g_csr[g_rowptr[d1.x] + r1.x] = s1.x;
        g_csr[g_rowptr[d1.y] + r1.y] = s1.y;
        g_csr[g_rowptr[d1.z] + r1.z] = s1.z;
        g_csr[g_rowptr[d1.w] + r1.w] = s1.w;
    } else {
        for (int e = base; e < nE; e++)
            g_csr[g_rowptr[dst[e]] + g_rank[e]] = src[e];
    }
}

// ------------------------------------------------- CSR gather aggregation (fp16 rows)
// 4-way unrolled inner loop: 4 shfls + 4 independent loads + 2 accumulators
__global__ void __launch_bounds__(256) agg_kernel(__nv_bfloat16* __restrict__ Zh,
                                                  __nv_bfloat16* __restrict__ Zl,
                                                  int nrows) {
    int warp = threadIdx.x >> 5;
    int lane = threadIdx.x & 31;
    int node = blockIdx.x * 8 + warp;
    if (node >= nrows) return;
    const uint2* H2 = (const uint2*)g_Hh;
    uint2 m = H2[(size_t)node * 32 + lane];
    float2 f0 = __half22float2(*(__half2*)&m.x);
    float2 f1 = __half22float2(*(__half2*)&m.y);
    float4 acc = make_float4(f0.x, f0.y, f1.x, f1.y);
    float4 acc1 = make_float4(0.f, 0.f, 0.f, 0.f);
    int beg = g_rowptr[node];
    int end = g_rowptr[node + 1];
    for (int base = beg; base < end; base += 32) {
        int cnt = min(32, end - base);
        int idx = (lane < cnt) ? g_csr[base + lane] : 0;
        int j = 0;
        for (; j + 3 < cnt; j += 4) {
            int s0 = __shfl_sync(0xFFFFFFFFu, idx, j);
            int s1 = __shfl_sync(0xFFFFFFFFu, idx, j + 1);
            int s2 = __shfl_sync(0xFFFFFFFFu, idx, j + 2);
            int s3 = __shfl_sync(0xFFFFFFFFu, idx, j + 3);
            uint2 v0 = H2[(size_t)s0 * 32 + lane];
            uint2 v1 = H2[(size_t)s1 * 32 + lane];
            uint2 v2 = H2[(size_t)s2 * 32 + lane];
            uint2 v3 = H2[(size_t)s3 * 32 + lane];
            float2 a0 = __half22float2(*(__half2*)&v0.x);
            float2 b0 = __half22float2(*(__half2*)&v0.y);
            float2 a1 = __half22float2(*(__half2*)&v1.x);
            float2 b1 = __half22float2(*(__half2*)&v1.y);
            float2 a2 = __half22float2(*(__half2*)&v2.x);
            float2 b2 = __half22float2(*(__half2*)&v2.y);
            float2 a3 = __half22float2(*(__half2*)&v3.x);
            float2 b3 = __half22float2(*(__half2*)&v3.y);
            acc.x  += a0.x + a2.x; acc.y  += a0.y + a2.y;
            acc.z  += b0.x + b2.x; acc.w  += b0.y + b2.y;
            acc1.x += a1.x + a3.x; acc1.y += a1.y + a3.y;
            acc1.z += b1.x + b3.x; acc1.w += b1.y + b3.y;
        }
        for (; j < cnt; j++) {
            int s = __shfl_sync(0xFFFFFFFFu, idx, j);
            uint2 v = H2[(size_t)s * 32 + lane];
            float2 a = __half22float2(*(__half2*)&v.x);
            float2 b = __half22float2(*(__half2*)&v.y);
            acc.x += a.x; acc.y += a.y; acc.z += b.x; acc.w += b.y;
        }
    }
    acc.x += acc1.x; acc.y += acc1.y; acc.z += acc1.z; acc.w += acc1.w;

    __nv_bfloat16 hx = __float2bfloat16(acc.x), hy = __float2bfloat16(acc.y);
    __nv_bfloat16 hz = __float2bfloat16(acc.z), hw = __float2bfloat16(acc.w);
    __nv_bfloat162 h0(hx, hy), h1(hz, hw);
    __nv_bfloat162 l0(__float2bfloat16(acc.x - __bfloat162float(hx)),
                      __float2bfloat16(acc.y - __bfloat162float(hy)));
    __nv_bfloat162 l1(__float2bfloat16(acc.z - __bfloat162float(hz)),
                      __float2bfloat16(acc.w - __bfloat162float(hw)));
    uint2 ph = make_uint2(*(uint32_t*)&h0, *(uint32_t*)&h1);
    uint2 pl = make_uint2(*(uint32_t*)&l0, *(uint32_t*)&l1);
    ((uint2*)(Zh + (size_t)node * HD))[lane] = ph;
    ((uint2*)(Zl + (size_t)node * HD))[lane] = pl;
}

// ================================================================ persistent fused layer
#define OFF_W1  0
#define OFF_W2  69632
#define OFF_A   139264
#define OFF_B1  208896
#define OFF_B2  209408
#define SMEM_L  209920

#define MMA16816(d, a, b0, b1) \
    asm volatile("mma.sync.aligned.m16n8k16.row.col.f32.bf16.bf16.f32 " \
        "{%0,%1,%2,%3}, {%4,%5,%6,%7}, {%8,%9}, {%0,%1,%2,%3};" \
        : "+f"((d)[0]), "+f"((d)[1]), "+f"((d)[2]), "+f"((d)[3]) \
        : "r"((a)[0]), "r"((a)[1]), "r"((a)[2]), "r"((a)[3]), "r"(b0), "r"(b1))

__device__ __forceinline__ void mainloop_128(const char* __restrict__ smemA,
                                             const char* __restrict__ smemB,
                                             float acc[16][4],
                                             int wm, int wn, int qrow, int qk) {
    const char* aH = smemA + (size_t)(wm * 32 + qrow) * 272;
    const char* aL = smemA + 34816 + (size_t)(wm * 32 + qrow) * 272;
    const char* bH = smemB + (size_t)(wn * 64 + qrow) * 272;
    const char* bL = smemB + 34816 + (size_t)(wn * 64 + qrow) * 272;
    #pragma unroll
    for (int kt = 0; kt < 8; kt++) {
        int kb = (kt * 16 + qk) * 2;
        uint32_t ah[2][4], al[2][4];
        #pragma unroll
        for (int mt = 0; mt < 2; mt++) {
            const char* pH = aH + mt * 16 * 272;
            const char* pL = aL + mt * 16 * 272;
            ah[mt][0] = *(const uint32_t*)(pH + kb);
            ah[mt][1] = *(const uint32_t*)(pH + 8 * 272 + kb);
            ah[mt][2] = *(const uint32_t*)(pH + kb + 16);
            ah[mt][3] = *(const uint32_t*)(pH + 8 * 272 + kb + 16);
            al[mt][0] = *(const uint32_t*)(pL + kb);
            al[mt][1] = *(const uint32_t*)(pL + 8 * 272 + kb);
            al[mt][2] = *(const uint32_t*)(pL + kb + 16);
            al[mt][3] = *(const uint32_t*)(pL + 8 * 272 + kb + 16);
        }
        #pragma unroll
        for (int nt = 0; nt < 8; nt++) {
            const char* pBh = bH + nt * 8 * 272;
            const char* pBl = bL + nt * 8 * 272;
            uint32_t bh0 = *(const uint32_t*)(pBh + kb);
            uint32_t bh1 = *(const uint32_t*)(pBh + kb + 16);
            uint32_t bl0 = *(const uint32_t*)(pBl + kb);
            uint32_t bl1 = *(const uint32_t*)(pBl + kb + 16);
            #pragma unroll
            for (int mt = 0; mt < 2; mt++) {
                MMA16816(acc[mt * 8 + nt], ah[mt], bh0, bh1);
                MMA16816(acc[mt * 8 + nt], al[mt], bh0, bh1);
                MMA16816(acc[mt * 8 + nt], ah[mt], bl0, bl1);
            }
        }
    }
}

template<bool HALF_OUT>
__global__ void __launch_bounds__(256) layer_kernel(
    const __nv_bfloat16* __restrict__ Zh, const __nv_bfloat16* __restrict__ Zl,
    const __nv_bfloat16* __restrict__ W1h, const __nv_bfloat16* __restrict__ W1l,
    const __nv_bfloat16* __restrict__ W2h, const __nv_bfloat16* __restrict__ W2l,
    const float* __restrict__ b1, const float* __restrict__ b2,
    float* __restrict__ O, __half* __restrict__ Oh16, int nrows, int ntiles)
{
    extern __shared__ char smem[];
    int tid = threadIdx.x, wid = tid >> 5, lane = tid & 31;
    int wm = wid >> 1, wn = wid & 1;
    int qrow = lane >> 2;
    int qk = (lane & 3) * 2;

    // ---- stage W1 + W2 + biases ONCE
    {
        const uint4* B1h4 = (const uint4*)W1h;
        const uint4* B1l4 = (const uint4*)W1l;
        const uint4* B2h4 = (const uint4*)W2h;
        const uint4* B2l4 = (const uint4*)W2l;
        #pragma unroll
        for (int i = tid; i < 2048; i += 256) {
            int r = i >> 4, c = i & 15;
            *(uint4*)(smem + OFF_W1 + r * 272 + c * 16) = B1h4[i];
            *(uint4*)(smem + OFF_W1 + 34816 + r * 272 + c * 16) = B1l4[i];
            *(uint4*)(smem + OFF_W2 + r * 272 + c * 16) = B2h4[i];
            *(uint4*)(smem + OFF_W2 + 34816 + r * 272 + c * 16) = B2l4[i];
        }
        if (tid < 128) {
            ((float*)(smem + OFF_B1))[tid] = b1[tid];
            ((float*)(smem + OFF_B2))[tid] = b2[tid];
        }
    }

    for (int tile = blockIdx.x; tile < ntiles; tile += gridDim.x) {
        int row0 = tile * 128;
        __syncthreads();

        // ---- stage A tile (z planes)
        {
            const uint4* Ah4 = (const uint4*)Zh + (size_t)row0 * 16;
            const uint4* Al4 = (const uint4*)Zl + (size_t)row0 * 16;
            #pragma unroll
            for (int i = tid; i < 2048; i += 256) {
                int r = i >> 4, c = i & 15;
                *(uint4*)(smem + OFF_A + r * 272 + c * 16) = Ah4[i];
                *(uint4*)(smem + OFF_A + 34816 + r * 272 + c * 16) = Al4[i];
            }
        }
        __syncthreads();

        float acc[16][4];
        #pragma unroll
        for (int i = 0; i < 16; i++) {
            acc[i][0] = 0.f; acc[i][1] = 0.f; acc[i][2] = 0.f; acc[i][3] = 0.f;
        }

        // ---- pass 1: t = relu(z@W1 + b1)
        mainloop_128(smem + OFF_A, smem + OFF_W1, acc, wm, wn, qrow, qk);
        __syncthreads();

        // write t (split) into A region
        {
            const float* sB1 = (const float*)(smem + OFF_B1);
            #pragma unroll
            for (int mt = 0; mt < 2; mt++) {
                #pragma unroll
                for (int nt = 0; nt < 8; nt++) {
                    int lr = wm * 32 + mt * 16 + qrow;
                    int col = wn * 64 + nt * 8 + qk;
                    float* a = acc[mt * 8 + nt];
                    float bx = sB1[col], by = sB1[col + 1];
                    #pragma unroll
                    for (int half = 0; half < 2; half++) {
                        int r = lr + half * 8;
                        float ox = fmaxf(a[half * 2 + 0] + bx, 0.f);
                        float oy = fmaxf(a[half * 2 + 1] + by, 0.f);
                        __nv_bfloat16 hx = __float2bfloat16(ox);
                        __nv_bfloat16 hy = __float2bfloat16(oy);
                        __nv_bfloat162 hp(hx, hy);
                        __nv_bfloat162 lp(__float2bfloat16(ox - __bfloat162float(hx)),
                                          __float2bfloat16(oy - __bfloat162float(hy)));
                        *(uint32_t*)(smem + OFF_A + r * 272 + col * 2) = *(uint32_t*)&hp;
                        *(uint32_t*)(smem + OFF_A + 34816 + r * 272 + col * 2) = *(uint32_t*)&lp;
                    }
                }
            }
        }
        __syncthreads();

        #pragma unroll
        for (int i = 0; i < 16; i++) {
            acc[i][0] = 0.f; acc[i][1] = 0.f; acc[i][2] = 0.f; acc[i][3] = 0.f;
        }

        // ---- pass 2: h = relu(t@W2 + b2)
        mainloop_128(smem + OFF_A, smem + OFF_W2, acc, wm, wn, qrow, qk);

        const float* sB2 = (const float*)(smem + OFF_B2);
        #pragma unroll
        for (int mt = 0; mt < 2; mt++) {
            #pragma unroll
            for (int nt = 0; nt < 8; nt++) {
                int row = row0 + wm * 32 + mt * 16 + qrow;
                int col = wn * 64 + nt * 8 + qk;
                float* a = acc[mt * 8 + nt];
                float bx = sB2[col], by = sB2[col + 1];
                #pragma unroll
                for (int half = 0; half < 2; half++) {
                    int rr = row + half * 8;
                    if (rr < nrows) {
                        float ox = fmaxf(a[half * 2 + 0] + bx, 0.f);
                        float oy = fmaxf(a[half * 2 + 1] + by, 0.f);
                        if (HALF_OUT) {
                            __half2 p = __floats2half2_rn(ox, oy);
                            *(uint32_t*)(Oh16 + (size_t)rr * HD + col) = *(uint32_t*)&p;
                        } else {
                            float2 o; o.x = ox; o.y = oy;
                            *(float2*)(O + (size_t)rr * HD + col) = o;
                        }
                    }
                }
            }
        }
    }
}

// ---------------------------------------------------------------- pooling
__global__ void pool_kernel(const float* __restrict__ Hf, const int* __restrict__ gid,
                            int nrows) {
    __shared__ float s[GG * HD];
    __shared__ float sc[GG];
    int tid = threadIdx.x;  // 128
    int start = blockIdx.x * 128;
    int end = min(start + 128, nrows);
    int gmin = __ldg(gid + start);
    int gmax = __ldg(gid + end - 1);
    for (int g = gmin; g <= gmax; g++) s[(g << 7) + tid] = 0.f;
    if (tid == 0) for (int g = gmin; g <= gmax; g++) sc[g] = 0.f;
    __syncthreads();
    for (int r = start; r < end; r++) {
        int g = __ldg(gid + r);
        s[(g << 7) + tid] += Hf[(size_t)r * HD + tid];
        if (tid == 0) sc[g] += 1.f;
    }
    __syncthreads();
    for (int g = gmin; g <= gmax; g++) atomicAdd(&g_sums[(g << 7) + tid], s[(g << 7) + tid]);
    if (tid == 0) for (int g = gmin; g <= gmax; g++) atomicAdd(&g_cnt[g], sc[g]);
}

// ---------------------------------------------------------------- classifier
__global__ void cls_kernel(const float* __restrict__ Wc1, const float* __restrict__ bc1,
                           const float* __restrict__ Wc2, const float* __restrict__ bc2,
                           float* __restrict__ out) {
    __shared__ float hg[GG * HD];
    __shared__ float t1[GG * HD];
    int tid = threadIdx.x;  // 256
    for (int i = tid; i < GG * HD; i += 256) {
        int g = i >> 7;
        hg[i] = g_sums[i] / fmaxf(g_cnt[g], 1.f);
    }
    __syncthreads();
    for (int i = tid; i < GG * HD; i += 256) {
        int g = i >> 7, c = i & 127;
        float a = bc1[c];
        #pragma unroll 8
        for (int k = 0; k < HD; k++) a += hg[(g << 7) + k] * Wc1[k * HD + c];
        t1[i] = fmaxf(a, 0.f);
    }
    __syncthreads();
    for (int i = tid; i < GG * 10; i += 256) {
        int g = i / 10, c = i - g * 10;
        float a = bc2[c];
        #pragma unroll 8
        for (int k = 0; k < HD; k++) a += t1[(g << 7) + k] * Wc2[k * 10 + c];
        out[i] = a;
    }
}

// ---------------------------------------------------------------- launch
extern "C" void kernel_launch(void* const* d_in, const int* in_sizes, int n_in,
                              void* d_out, int out_size) {
    const float* h   = (const float*)d_in[0];
    const int*   src = (const int*)d_in[1];
    const int*   dst = (const int*)d_in[2];
    const int*   gid = (const int*)d_in[3];
    const float* W1a = (const float*)d_in[4];  const float* b1a = (const float*)d_in[5];
    const float* W2a = (const float*)d_in[6];  const float* b2a = (const float*)d_in[7];
    const float* W1b = (const float*)d_in[8];  const float* b1b = (const float*)d_in[9];
    const float* W2b = (const float*)d_in[10]; const float* b2b = (const float*)d_in[11];
    const float* Wc1 = (const float*)d_in[12]; const float* bc1 = (const float*)d_in[13];
    const float* Wc2 = (const float*)d_in[14]; const float* bc2 = (const float*)d_in[15];
    float* out = (float*)d_out;

    int N = in_sizes[0] / HD;
    int E = in_sizes[1];

    float* A;
    __half* Hh;
    __nv_bfloat16 *Zh, *Zl, *Wh, *Wl;
    cudaGetSymbolAddress((void**)&A, g_A);
    cudaGetSymbolAddress((void**)&Hh, g_Hh);
    cudaGetSymbolAddress((void**)&Zh, g_Zh);
    cudaGetSymbolAddress((void**)&Zl, g_Zl);
    cudaGetSymbolAddress((void**)&Wh, g_Wbh);
    cudaGetSymbolAddress((void**)&Wl, g_Wbl);

    cudaFuncSetAttribute(layer_kernel<false>, cudaFuncAttributeMaxDynamicSharedMemorySize, SMEM_L);
    cudaFuncSetAttribute(layer_kernel<true>,  cudaFuncAttributeMaxDynamicSharedMemorySize, SMEM_L);

    int n4 = N * 32;
    int pb = (n4 + 255) / 256;
    int eb8 = ((E + 7) / 8 + 255) / 256;
    int ab = (N + 7) / 8;
    int ntiles = (N + 127) / 128;
    int lg = ntiles < 148 ? ntiles : 148;
    int sb = (N + 8191) / 8192;

    // prep (+fp16 convert), CSR build
    prep_kernel<<<pb, 256>>>(h, W1a, W2a, W1b, W2b, N, n4);
    hist_kernel<<<eb8, 256>>>(dst, E);
    scan_fused_kernel<<<sb, 1024>>>(N);
    fill_kernel<<<eb8, 256>>>(src, dst, E);

    // Layer A: agg(fp16 h) -> persistent fused double-GEMM -> h1 fp16
    agg_kernel<<<ab, 256>>>(Zh, Zl, N);
    layer_kernel<true><<<lg, 256, SMEM_L>>>(Zh, Zl,
                                            Wh + 0 * 16384, Wl + 0 * 16384,
                                            Wh + 1 * 16384, Wl + 1 * 16384,
                                            b1a, b2a, nullptr, Hh, N, ntiles);
    // Layer B: agg(fp16 h1) -> persistent fused double-GEMM -> h2 fp32
    agg_kernel<<<ab, 256>>>(Zh, Zl, N);
    layer_kernel<false><<<lg, 256, SMEM_L>>>(Zh, Zl,
                                             Wh + 2 * 16384, Wl + 2 * 16384,
                                             Wh + 3 * 16384, Wl + 3 * 16384,
                                             b1b, b2b, A, nullptr, N, ntiles);
    // Readout + classifier
    pool_kernel<<<(N + 127) / 128, 128>>>(A, gid, N);
    cls_kernel<<<1, 256>>>(Wc1, bc1, Wc2, bc2, out);
}

// round 17
// speedup vs baseline: 1.0439x; 1.0439x over previous
#include <cuda_runtime.h>
#include <cuda_bf16.h>
#include <cuda_fp16.h>
#include <cstdint>

#define NMAX 50048
#define EMAX 800000
#define HD   128
#define GG   16

// Scratch (no cudaMalloc allowed)
__device__ __align__(256) __half g_Hh[NMAX * HD];              // fp16 features (h -> h1 -> h2)
__device__ __align__(16) __nv_bfloat16 g_Zh[NMAX * HD];
__device__ __align__(16) __nv_bfloat16 g_Zl[NMAX * HD];
__device__ float g_sums[GG * HD];
__device__ float g_cnt[GG];
__device__ __align__(16) int g_rowptr[NMAX + 8];
__device__ __align__(16) int g_cursor[NMAX];
__device__ __align__(16) int g_rank[EMAX];
__device__ __align__(16) int g_csr[EMAX];
__device__ int   g_bflag[64];
__device__ int   g_bagg[64];
__device__ int   g_bincl[64];
__device__ __align__(16) __nv_bfloat16 g_Wbh[4 * 16384];
__device__ __align__(16) __nv_bfloat16 g_Wbl[4 * 16384];

// ================================================================ prep (+ h->fp16)
__global__ void prep_kernel(const float* __restrict__ h,
                            const float* __restrict__ W1a, const float* __restrict__ W2a,
                            const float* __restrict__ W1b, const float* __restrict__ W2b,
                            int n, int n4) {
    int idx = blockIdx.x * 256 + threadIdx.x;
    if (idx < n4) {
        float4 v = ((const float4*)h)[idx];
        __half2 a = __floats2half2_rn(v.x, v.y);
        __half2 b = __floats2half2_rn(v.z, v.w);
        uint2 p;
        p.x = *(uint32_t*)&a;
        p.y = *(uint32_t*)&b;
        ((uint2*)g_Hh)[idx] = p;
    }
    if (idx < n)  g_cursor[idx] = 0;
    if (idx < 64) g_bflag[idx] = 0;
    if (idx < GG * HD) g_sums[idx] = 0.f;
    if (idx < GG) g_cnt[idx] = 0.f;
    if (idx < 65536) {
        int w = idx >> 14, rem = idx & 16383;
        int nn = rem >> 7, k = rem & 127;
        const float* Wp = (w == 0) ? W1a : (w == 1) ? W2a : (w == 2) ? W1b : W2b;
        float v = Wp[k * 128 + nn];
        __nv_bfloat16 hi = __float2bfloat16(v);
        __nv_bfloat16 lo = __float2bfloat16(v - __bfloat162float(hi));
        g_Wbh[idx] = hi;
        g_Wbl[idx] = lo;
    }
}

// hist + rank, 8 edges/thread
__global__ void hist_kernel(const int* __restrict__ dst, int nE) {
    int base = (blockIdx.x * blockDim.x + threadIdx.x) * 8;
    if (base + 7 < nE) {
        int4 d0 = *(const int4*)(dst + base);
        int4 d1 = *(const int4*)(dst + base + 4);
        int r0 = atomicAdd(&g_cursor[d0.x], 1);
        int r1 = atomicAdd(&g_cursor[d0.y], 1);
        int r2 = atomicAdd(&g_cursor[d0.z], 1);
        int r3 = atomicAdd(&g_cursor[d0.w], 1);
        int r4 = atomicAdd(&g_cursor[d1.x], 1);
        int r5 = atomicAdd(&g_cursor[d1.y], 1);
        int r6 = atomicAdd(&g_cursor[d1.z], 1);
        int r7 = atomicAdd(&g_cursor[d1.w], 1);
        *(int4*)(g_rank + base)     = make_int4(r0, r1, r2, r3);
        *(int4*)(g_rank + base + 4) = make_int4(r4, r5, r6, r7);
    } else {
        for (int e = base; e < nE; e++) g_rank[e] = atomicAdd(&g_cursor[dst[e]], 1);
    }
}

// ---------------- decoupled-lookback scan, 8 counts/thread
__global__ void __launch_bounds__(1024) scan_fused_kernel(int n) {
    __shared__ int warpsums[32];
    __shared__ int s_off;
    int tid = threadIdx.x, lane = tid & 31, w = tid >> 5;
    int bid = blockIdx.x;
    int i8 = (bid * 1024 + tid) * 8;

    int v[8];
    if (i8 + 7 < n) {
        int4 a = *(const int4*)(g_cursor + i8);
        int4 b = *(const int4*)(g_cursor + i8 + 4);
        v[0] = a.x; v[1] = a.y; v[2] = a.z; v[3] = a.w;
        v[4] = b.x; v[5] = b.y; v[6] = b.z; v[7] = b.w;
    } else {
        #pragma unroll
        for (int j = 0; j < 8; j++) v[j] = (i8 + j < n) ? g_cursor[i8 + j] : 0;
    }
    int tsum = 0;
    #pragma unroll
    for (int j = 0; j < 8; j++) tsum += v[j];

    int x = tsum;
    #pragma unroll
    for (int o = 1; o < 32; o <<= 1) {
        int y = __shfl_up_sync(0xFFFFFFFFu, x, o);
        if (lane >= o) x += y;
    }
    if (lane == 31) warpsums[w] = x;
    __syncthreads();
    if (w == 0) {
        int y = warpsums[lane];
        #pragma unroll
        for (int o = 1; o < 32; o <<= 1) {
            int z = __shfl_up_sync(0xFFFFFFFFu, y, o);
            if (lane >= o) y += z;
        }
        warpsums[lane] = y;
    }
    __syncthreads();
    int incl = x + (w > 0 ? warpsums[w - 1] : 0);
    int total = warpsums[31];

    if (tid == 0) {
        if (bid == 0) {
            g_bincl[0] = total;
            __threadfence();
            atomicExch(&g_bflag[0], 2);
            s_off = 0;
        } else {
            g_bagg[bid] = total;
            __threadfence();
            atomicExch(&g_bflag[bid], 1);
            int run = 0, p = bid - 1;
            while (true) {
                int f;
                do { f = atomicAdd(&g_bflag[p], 0); } while (f == 0);
                if (f == 2) { run += atomicAdd(&g_bincl[p], 0); break; }
                run += atomicAdd(&g_bagg[p], 0);
                p--;
            }
            g_bincl[bid] = run + total;
            __threadfence();
            atomicExch(&g_bflag[bid], 2);
            s_off = run;
        }
    }
    __syncthreads();
    int run = s_off + incl - tsum;
    #pragma unroll
    for (int j = 0; j < 8; j++) {
        run += v[j];
        if (i8 + j < n) g_rowptr[i8 + j + 1] = run;
    }
    if (i8 == 0) g_rowptr[0] = 0;
}

// atomic-free fill, 8 edges/thread
__global__ void fill_kernel(const int* __restrict__ src, const int* __restrict__ dst, int nE) {
    int base = (blockIdx.x * blockDim.x + threadIdx.x) * 8;
    if (base + 7 < nE) {
        int4 d0 = *(const int4*)(dst + base);
        int4 d1 = *(const int4*)(dst + base + 4);
        int4 s0 = *(const int4*)(src + base);
        int4 s1 = *(const int4*)(src + base + 4);
        int4 r0 = *(const int4*)(g_rank + base);
        int4 r1 = *(const int4*)(g_rank + base + 4);
        g_csr[g_rowptr[d0.x] + r0.x] = s0.x;
        g_csr[g_rowptr[d0.y] + r0.y] = s0.y;
        g_csr[g_rowptr[d0.z] + r0.z] = s0.z;
        g_csr[g_rowptr[d0.w] + r0.w] = s0.w;
        g_csr[g_rowptr[d1.x] + r1.x] = s1.x;
        g_csr[g_rowptr[d1.y] + r1.y] = s1.y;
        g_csr[g_rowptr[d1.z] + r1.z] = s1.z;
        g_csr[g_rowptr[d1.w] + r1.w] = s1.w;
    } else {
        for (int e = base; e < nE; e++)
            g_csr[g_rowptr[dst[e]] + g_rank[e]] = src[e];
    }
}

// ------------------------------------------------- CSR gather aggregation (fp16 rows)
// simple loop (R15 form — 4-way unroll measured as regression)
__global__ void __launch_bounds__(256) agg_kernel(__nv_bfloat16* __restrict__ Zh,
                                                  __nv_bfloat16* __restrict__ Zl,
                                                  int nrows) {
    int warp = threadIdx.x >> 5;
    int lane = threadIdx.x & 31;
    int node = blockIdx.x * 8 + warp;
    if (node >= nrows) return;
    const uint2* H2 = (const uint2*)g_Hh;
    uint2 m = H2[(size_t)node * 32 + lane];
    float2 f0 = __half22float2(*(__half2*)&m.x);
    float2 f1 = __half22float2(*(__half2*)&m.y);
    float4 acc = make_float4(f0.x, f0.y, f1.x, f1.y);
    int beg = g_rowptr[node];
    int end = g_rowptr[node + 1];
    for (int base = beg; base < end; base += 32) {
        int cnt = min(32, end - base);
        int idx = (lane < cnt) ? g_csr[base + lane] : 0;
        for (int j = 0; j < cnt; j++) {
            int s = __shfl_sync(0xFFFFFFFFu, idx, j);
            uint2 v = H2[(size_t)s * 32 + lane];
            float2 a = __half22float2(*(__half2*)&v.x);
            float2 b = __half22float2(*(__half2*)&v.y);
            acc.x += a.x; acc.y += a.y; acc.z += b.x; acc.w += b.y;
        }
    }
    __nv_bfloat16 hx = __float2bfloat16(acc.x), hy = __float2bfloat16(acc.y);
    __nv_bfloat16 hz = __float2bfloat16(acc.z), hw = __float2bfloat16(acc.w);
    __nv_bfloat162 h0(hx, hy), h1(hz, hw);
    __nv_bfloat162 l0(__float2bfloat16(acc.x - __bfloat162float(hx)),
                      __float2bfloat16(acc.y - __bfloat162float(hy)));
    __nv_bfloat162 l1(__float2bfloat16(acc.z - __bfloat162float(hz)),
                      __float2bfloat16(acc.w - __bfloat162float(hw)));
    uint2 ph = make_uint2(*(uint32_t*)&h0, *(uint32_t*)&h1);
    uint2 pl = make_uint2(*(uint32_t*)&l0, *(uint32_t*)&l1);
    ((uint2*)(Zh + (size_t)node * HD))[lane] = ph;
    ((uint2*)(Zl + (size_t)node * HD))[lane] = pl;
}

// ================================================================ persistent fused layer
// Both layers emit fp16 into g_Hh (layer A: h1 for next agg; layer B: h2 for pool).
#define OFF_W1  0
#define OFF_W2  69632
#define OFF_A   139264
#define OFF_B1  208896
#define OFF_B2  209408
#define SMEM_L  209920

#define MMA16816(d, a, b0, b1) \
    asm volatile("mma.sync.aligned.m16n8k16.row.col.f32.bf16.bf16.f32 " \
        "{%0,%1,%2,%3}, {%4,%5,%6,%7}, {%8,%9}, {%0,%1,%2,%3};" \
        : "+f"((d)[0]), "+f"((d)[1]), "+f"((d)[2]), "+f"((d)[3]) \
        : "r"((a)[0]), "r"((a)[1]), "r"((a)[2]), "r"((a)[3]), "r"(b0), "r"(b1))

__device__ __forceinline__ void mainloop_128(const char* __restrict__ smemA,
                                             const char* __restrict__ smemB,
                                             float acc[16][4],
                                             int wm, int wn, int qrow, int qk) {
    const char* aH = smemA + (size_t)(wm * 32 + qrow) * 272;
    const char* aL = smemA + 34816 + (size_t)(wm * 32 + qrow) * 272;
    const char* bH = smemB + (size_t)(wn * 64 + qrow) * 272;
    const char* bL = smemB + 34816 + (size_t)(wn * 64 + qrow) * 272;
    #pragma unroll
    for (int kt = 0; kt < 8; kt++) {
        int kb = (kt * 16 + qk) * 2;
        uint32_t ah[2][4], al[2][4];
        #pragma unroll
        for (int mt = 0; mt < 2; mt++) {
            const char* pH = aH + mt * 16 * 272;
            const char* pL = aL + mt * 16 * 272;
            ah[mt][0] = *(const uint32_t*)(pH + kb);
            ah[mt][1] = *(const uint32_t*)(pH + 8 * 272 + kb);
            ah[mt][2] = *(const uint32_t*)(pH + kb + 16);
            ah[mt][3] = *(const uint32_t*)(pH + 8 * 272 + kb + 16);
            al[mt][0] = *(const uint32_t*)(pL + kb);
            al[mt][1] = *(const uint32_t*)(pL + 8 * 272 + kb);
            al[mt][2] = *(const uint32_t*)(pL + kb + 16);
            al[mt][3] = *(const uint32_t*)(pL + 8 * 272 + kb + 16);
        }
        #pragma unroll
        for (int nt = 0; nt < 8; nt++) {
            const char* pBh = bH + nt * 8 * 272;
            const char* pBl = bL + nt * 8 * 272;
            uint32_t bh0 = *(const uint32_t*)(pBh + kb);
            uint32_t bh1 = *(const uint32_t*)(pBh + kb + 16);
            uint32_t bl0 = *(const uint32_t*)(pBl + kb);
            uint32_t bl1 = *(const uint32_t*)(pBl + kb + 16);
            #pragma unroll
            for (int mt = 0; mt < 2; mt++) {
                MMA16816(acc[mt * 8 + nt], ah[mt], bh0, bh1);
                MMA16816(acc[mt * 8 + nt], al[mt], bh0, bh1);
                MMA16816(acc[mt * 8 + nt], ah[mt], bl0, bl1);
            }
        }
    }
}

__global__ void __launch_bounds__(256) layer_kernel(
    const __nv_bfloat16* __restrict__ Zh, const __nv_bfloat16* __restrict__ Zl,
    const __nv_bfloat16* __restrict__ W1h, const __nv_bfloat16* __restrict__ W1l,
    const __nv_bfloat16* __restrict__ W2h, const __nv_bfloat16* __restrict__ W2l,
    const float* __restrict__ b1, const float* __restrict__ b2,
    __half* __restrict__ Oh16, int nrows, int ntiles)
{
    extern __shared__ char smem[];
    int tid = threadIdx.x, wid = tid >> 5, lane = tid & 31;
    int wm = wid >> 1, wn = wid & 1;
    int qrow = lane >> 2;
    int qk = (lane & 3) * 2;

    // ---- stage W1 + W2 + biases ONCE
    {
        const uint4* B1h4 = (const uint4*)W1h;
        const uint4* B1l4 = (const uint4*)W1l;
        const uint4* B2h4 = (const uint4*)W2h;
        const uint4* B2l4 = (const uint4*)W2l;
        #pragma unroll
        for (int i = tid; i < 2048; i += 256) {
            int r = i >> 4, c = i & 15;
            *(uint4*)(smem + OFF_W1 + r * 272 + c * 16) = B1h4[i];
            *(uint4*)(smem + OFF_W1 + 34816 + r * 272 + c * 16) = B1l4[i];
            *(uint4*)(smem + OFF_W2 + r * 272 + c * 16) = B2h4[i];
            *(uint4*)(smem + OFF_W2 + 34816 + r * 272 + c * 16) = B2l4[i];
        }
        if (tid < 128) {
            ((float*)(smem + OFF_B1))[tid] = b1[tid];
            ((float*)(smem + OFF_B2))[tid] = b2[tid];
        }
    }

    for (int tile = blockIdx.x; tile < ntiles; tile += gridDim.x) {
        int row0 = tile * 128;
        __syncthreads();

        // ---- stage A tile (z planes)
        {
            const uint4* Ah4 = (const uint4*)Zh + (size_t)row0 * 16;
            const uint4* Al4 = (const uint4*)Zl + (size_t)row0 * 16;
            #pragma unroll
            for (int i = tid; i < 2048; i += 256) {
                int r = i >> 4, c = i & 15;
                *(uint4*)(smem + OFF_A + r * 272 + c * 16) = Ah4[i];
                *(uint4*)(smem + OFF_A + 34816 + r * 272 + c * 16) = Al4[i];
            }
        }
        __syncthreads();

        float acc[16][4];
        #pragma unroll
        for (int i = 0; i < 16; i++) {
            acc[i][0] = 0.f; acc[i][1] = 0.f; acc[i][2] = 0.f; acc[i][3] = 0.f;
        }

        // ---- pass 1: t = relu(z@W1 + b1)
        mainloop_128(smem + OFF_A, smem + OFF_W1, acc, wm, wn, qrow, qk);
        __syncthreads();

        // write t (split) into A region
        {
            const float* sB1 = (const float*)(smem + OFF_B1);
            #pragma unroll
            for (int mt = 0; mt < 2; mt++) {
                #pragma unroll
                for (int nt = 0; nt < 8; nt++) {
                    int lr = wm * 32 + mt * 16 + qrow;
                    int col = wn * 64 + nt * 8 + qk;
                    float* a = acc[mt * 8 + nt];
                    float bx = sB1[col], by = sB1[col + 1];
                    #pragma unroll
                    for (int half = 0; half < 2; half++) {
                        int r = lr + half * 8;
                        float ox = fmaxf(a[half * 2 + 0] + bx, 0.f);
                        float oy = fmaxf(a[half * 2 + 1] + by, 0.f);
                        __nv_bfloat16 hx = __float2bfloat16(ox);
                        __nv_bfloat16 hy = __float2bfloat16(oy);
                        __nv_bfloat162 hp(hx, hy);
                        __nv_bfloat162 lp(__float2bfloat16(ox - __bfloat162float(hx)),
                                          __float2bfloat16(oy - __bfloat162float(hy)));
                        *(uint32_t*)(smem + OFF_A + r * 272 + col * 2) = *(uint32_t*)&hp;
                        *(uint32_t*)(smem + OFF_A + 34816 + r * 272 + col * 2) = *(uint32_t*)&lp;
                    }
                }
            }
        }
        __syncthreads();

        #pragma unroll
        for (int i = 0; i < 16; i++) {
            acc[i][0] = 0.f; acc[i][1] = 0.f; acc[i][2] = 0.f; acc[i][3] = 0.f;
        }

        // ---- pass 2: h = relu(t@W2 + b2) -> fp16 out
        mainloop_128(smem + OFF_A, smem + OFF_W2, acc, wm, wn, qrow, qk);

        const float* sB2 = (const float*)(smem + OFF_B2);
        #pragma unroll
        for (int mt = 0; mt < 2; mt++) {
            #pragma unroll
            for (int nt = 0; nt < 8; nt++) {
                int row = row0 + wm * 32 + mt * 16 + qrow;
                int col = wn * 64 + nt * 8 + qk;
                float* a = acc[mt * 8 + nt];
                float bx = sB2[col], by = sB2[col + 1];
                #pragma unroll
                for (int half = 0; half < 2; half++) {
                    int rr = row + half * 8;
                    if (rr < nrows) {
                        float ox = fmaxf(a[half * 2 + 0] + bx, 0.f);
                        float oy = fmaxf(a[half * 2 + 1] + by, 0.f);
                        __half2 p = __floats2half2_rn(ox, oy);
                        *(uint32_t*)(Oh16 + (size_t)rr * HD + col) = *(uint32_t*)&p;
                    }
                }
            }
        }
    }
}

// ---------------------------------------------------------------- pooling (fp16 input)
__global__ void pool_kernel(const __half* __restrict__ Hf, const int* __restrict__ gid,
                            int nrows) {
    __shared__ float s[GG * HD];
    __shared__ float sc[GG];
    int tid = threadIdx.x;  // 128
    int start = blockIdx.x * 128;
    int end = min(start + 128, nrows);
    int gmin = __ldg(gid + start);
    int gmax = __ldg(gid + end - 1);
    for (int g = gmin; g <= gmax; g++) s[(g << 7) + tid] = 0.f;
    if (tid == 0) for (int g = gmin; g <= gmax; g++) sc[g] = 0.f;
    __syncthreads();
    for (int r = start; r < end; r++) {
        int g = __ldg(gid + r);
        s[(g << 7) + tid] += __half2float(Hf[(size_t)r * HD + tid]);
        if (tid == 0) sc[g] += 1.f;
    }
    __syncthreads();
    for (int g = gmin; g <= gmax; g++) atomicAdd(&g_sums[(g << 7) + tid], s[(g << 7) + tid]);
    if (tid == 0) for (int g = gmin; g <= gmax; g++) atomicAdd(&g_cnt[g], sc[g]);
}

// ---------------------------------------------------------------- classifier
__global__ void cls_kernel(const float* __restrict__ Wc1, const float* __restrict__ bc1,
                           const float* __restrict__ Wc2, const float* __restrict__ bc2,
                           float* __restrict__ out) {
    __shared__ float hg[GG * HD];
    __shared__ float t1[GG * HD];
    int tid = threadIdx.x;  // 256
    for (int i = tid; i < GG * HD; i += 256) {
        int g = i >> 7;
        hg[i] = g_sums[i] / fmaxf(g_cnt[g], 1.f);
    }
    __syncthreads();
    for (int i = tid; i < GG * HD; i += 256) {
        int g = i >> 7, c = i & 127;
        float a = bc1[c];
        #pragma unroll 8
        for (int k = 0; k < HD; k++) a += hg[(g << 7) + k] * Wc1[k * HD + c];
        t1[i] = fmaxf(a, 0.f);
    }
    __syncthreads();
    for (int i = tid; i < GG * 10; i += 256) {
        int g = i / 10, c = i - g * 10;
        float a = bc2[c];
        #pragma unroll 8
        for (int k = 0; k < HD; k++) a += t1[(g << 7) + k] * Wc2[k * 10 + c];
        out[i] = a;
    }
}

// ---------------------------------------------------------------- launch
extern "C" void kernel_launch(void* const* d_in, const int* in_sizes, int n_in,
                              void* d_out, int out_size) {
    const float* h   = (const float*)d_in[0];
    const int*   src = (const int*)d_in[1];
    const int*   dst = (const int*)d_in[2];
    const int*   gid = (const int*)d_in[3];
    const float* W1a = (const float*)d_in[4];  const float* b1a = (const float*)d_in[5];
    const float* W2a = (const float*)d_in[6];  const float* b2a = (const float*)d_in[7];
    const float* W1b = (const float*)d_in[8];  const float* b1b = (const float*)d_in[9];
    const float* W2b = (const float*)d_in[10]; const float* b2b = (const float*)d_in[11];
    const float* Wc1 = (const float*)d_in[12]; const float* bc1 = (const float*)d_in[13];
    const float* Wc2 = (const float*)d_in[14]; const float* bc2 = (const float*)d_in[15];
    float* out = (float*)d_out;

    int N = in_sizes[0] / HD;
    int E = in_sizes[1];

    __half* Hh;
    __nv_bfloat16 *Zh, *Zl, *Wh, *Wl;
    cudaGetSymbolAddress((void**)&Hh, g_Hh);
    cudaGetSymbolAddress((void**)&Zh, g_Zh);
    cudaGetSymbolAddress((void**)&Zl, g_Zl);
    cudaGetSymbolAddress((void**)&Wh, g_Wbh);
    cudaGetSymbolAddress((void**)&Wl, g_Wbl);

    cudaFuncSetAttribute(layer_kernel, cudaFuncAttributeMaxDynamicSharedMemorySize, SMEM_L);

    int n4 = N * 32;
    int pb = (n4 + 255) / 256;
    int eb8 = ((E + 7) / 8 + 255) / 256;
    int ab = (N + 7) / 8;
    int ntiles = (N + 127) / 128;
    int lg = ntiles < 148 ? ntiles : 148;
    int sb = (N + 8191) / 8192;

    // prep (+fp16 convert), CSR build
    prep_kernel<<<pb, 256>>>(h, W1a, W2a, W1b, W2b, N, n4);
    hist_kernel<<<eb8, 256>>>(dst, E);
    scan_fused_kernel<<<sb, 1024>>>(N);
    fill_kernel<<<eb8, 256>>>(src, dst, E);

    // Layer A: agg(fp16 h) -> persistent fused double-GEMM -> h1 fp16
    agg_kernel<<<ab, 256>>>(Zh, Zl, N);
    layer_kernel<<<lg, 256, SMEM_L>>>(Zh, Zl,
                                      Wh + 0 * 16384, Wl + 0 * 16384,
                                      Wh + 1 * 16384, Wl + 1 * 16384,
                                      b1a, b2a, Hh, N, ntiles);
    // Layer B: agg(fp16 h1) -> persistent fused double-GEMM -> h2 fp16
    agg_kernel<<<ab, 256>>>(Zh, Zl, N);
    layer_kernel<<<lg, 256, SMEM_L>>>(Zh, Zl,
                                      Wh + 2 * 16384, Wl + 2 * 16384,
                                      Wh + 3 * 16384, Wl + 3 * 16384,
                                      b1b, b2b, Hh, N, ntiles);
    // Readout + classifier
    pool_kernel<<<(N + 127) / 128, 128>>>(Hh, gid, N);
    cls_kernel<<<1, 256>>>(Wc1, bc1, Wc2, bc2, out);
}